// round 1
// baseline (speedup 1.0000x reference)
#include <cuda_runtime.h>
#include <math.h>

// ---------------- problem constants ----------------
#define B_    2
#define S_    1024
#define H_    2048
#define NH_   16
#define QLR_  1536
#define KVLR_ 512
#define NOPE_ 128
#define ROPE_ 64
#define VD_   128
#define QHD_  192
#define I_    8192
#define T_    (B_*S_)        // 2048 tokens
#define SCALE_ 0.07216878364870323f   // 192^-0.5
#define EPS_  1e-6f

// ---------------- scratch (__device__ globals; no allocations allowed) ----------------
__device__ float g_x[T_ * H_];            // rms(hidden)
__device__ float g_qa[T_ * QLR_];         // q_a (then rms'd in place)
__device__ float g_q[T_ * NH_ * QHD_];    // q_b output (raw, pre-rope)
__device__ float g_ckv[T_ * (KVLR_ + ROPE_)];
__device__ float g_ckvn[T_ * KVLR_];
__device__ float g_kv[T_ * NH_ * (NOPE_ + VD_)];
__device__ float g_qh[(size_t)B_ * NH_ * S_ * QHD_];  // (b,h,s,192) rope applied
__device__ float g_kh[(size_t)B_ * NH_ * S_ * QHD_];  // (b,h,s,192)
__device__ float g_vh[(size_t)B_ * NH_ * S_ * VD_];   // (b,h,s,128)
__device__ float g_scores[(size_t)B_ * NH_ * S_ * S_]; // attn probs in-place
__device__ float g_attnout[T_ * H_];      // (b,s, h*128+d)
__device__ float g_h1[T_ * H_];           // attn + residual
__device__ float g_y[T_ * H_];            // post rms
__device__ float g_gate[(size_t)T_ * I_];
__device__ float g_act[(size_t)T_ * I_];

// ---------------- rmsnorm: one block per row ----------------
__global__ void rms_kernel(const float* __restrict__ in, const float* __restrict__ w,
                           float* __restrict__ out, int D, int in_stride, int out_stride) {
    int t = blockIdx.x;
    const float* x = in + (size_t)t * in_stride;
    float* y = out + (size_t)t * out_stride;
    int tid = threadIdx.x;
    float ss = 0.f;
    for (int j = tid; j < D; j += blockDim.x) { float v = x[j]; ss += v * v; }
    __shared__ float red[256];
    red[tid] = ss; __syncthreads();
    for (int s = 128; s > 0; s >>= 1) { if (tid < s) red[tid] += red[tid + s]; __syncthreads(); }
    float scale = rsqrtf(red[0] / (float)D + EPS_);
    for (int j = tid; j < D; j += blockDim.x) y[j] = x[j] * scale * w[j];
}

// ---------------- generic tiled fp32 GEMM: C = A(MxK) @ B(KxN) ----------------
// EPI: 0 = store, 1 = acc + R, 2 = silu(R) * acc
#define BM 128
#define BN 128
#define BK 8
#define TM 8
#define TN 8

template<int EPI>
__global__ void gemm_kernel(const float* __restrict__ A, const float* __restrict__ Bm,
                            float* __restrict__ C, const float* __restrict__ R,
                            int M, int N, int K) {
    __shared__ float As[BK][BM];
    __shared__ float Bs[BK][BN];
    int bm = blockIdx.y, bn = blockIdx.x;
    int tid = threadIdx.x;
    int tx = tid & 15, ty = tid >> 4;
    int row0 = bm * BM, col0 = bn * BN;
    int a_row = tid >> 1, a_col = (tid & 1) * 4;
    int b_row = tid >> 5, b_col = (tid & 31) * 4;
    float acc[TM][TN];
#pragma unroll
    for (int i = 0; i < TM; i++)
#pragma unroll
        for (int j = 0; j < TN; j++) acc[i][j] = 0.f;

    for (int k0 = 0; k0 < K; k0 += BK) {
        float4 av = *(const float4*)&A[(size_t)(row0 + a_row) * K + k0 + a_col];
        As[a_col + 0][a_row] = av.x;
        As[a_col + 1][a_row] = av.y;
        As[a_col + 2][a_row] = av.z;
        As[a_col + 3][a_row] = av.w;
        int gcol = col0 + b_col;
        float4 bv = make_float4(0.f, 0.f, 0.f, 0.f);
        if (gcol < N) bv = *(const float4*)&Bm[(size_t)(k0 + b_row) * N + gcol];
        *(float4*)&Bs[b_row][b_col] = bv;
        __syncthreads();
#pragma unroll
        for (int k = 0; k < BK; k++) {
            float ra[TM], rb[TN];
#pragma unroll
            for (int i = 0; i < TM; i++) ra[i] = As[k][ty * TM + i];
#pragma unroll
            for (int j = 0; j < TN; j++) rb[j] = Bs[k][tx * TN + j];
#pragma unroll
            for (int i = 0; i < TM; i++)
#pragma unroll
                for (int j = 0; j < TN; j++) acc[i][j] += ra[i] * rb[j];
        }
        __syncthreads();
    }
#pragma unroll
    for (int i = 0; i < TM; i++) {
        int r = row0 + ty * TM + i;
#pragma unroll
        for (int j = 0; j < TN; j += 4) {
            int c = col0 + tx * TN + j;
            if (c < N) {
                float4 v = make_float4(acc[i][j], acc[i][j+1], acc[i][j+2], acc[i][j+3]);
                if (EPI == 1) {
                    float4 rr = *(const float4*)&R[(size_t)r * N + c];
                    v.x += rr.x; v.y += rr.y; v.z += rr.z; v.w += rr.w;
                } else if (EPI == 2) {
                    float4 rr = *(const float4*)&R[(size_t)r * N + c];
                    v.x *= rr.x / (1.f + __expf(-rr.x));
                    v.y *= rr.y / (1.f + __expf(-rr.y));
                    v.z *= rr.z / (1.f + __expf(-rr.z));
                    v.w *= rr.w / (1.f + __expf(-rr.w));
                }
                *(float4*)&C[(size_t)r * N + c] = v;
            }
        }
    }
}

// ---------------- assemble (b,h,s,d) layouts + fused RoPE ----------------
__global__ void assemble_kernel(const float* __restrict__ q, const float* __restrict__ kv,
                                const float* __restrict__ ckv,
                                const float* __restrict__ cosT, const float* __restrict__ sinT,
                                const int* __restrict__ pos_ids,
                                float* __restrict__ qh, float* __restrict__ kh,
                                float* __restrict__ vh) {
    int t = blockIdx.x;             // token
    int b = t / S_, s = t % S_;
    int tid = threadIdx.x;
    int pos = pos_ids[t];
    __shared__ float kpe[ROPE_];
    if (tid < 32) {
        int j = tid;
        float x0 = ckv[(size_t)t * (KVLR_ + ROPE_) + KVLR_ + 2 * j];
        float x1 = ckv[(size_t)t * (KVLR_ + ROPE_) + KVLR_ + 2 * j + 1];
        float c0 = cosT[pos * ROPE_ + j],      sn0 = sinT[pos * ROPE_ + j];
        float c1 = cosT[pos * ROPE_ + 32 + j], sn1 = sinT[pos * ROPE_ + 32 + j];
        kpe[j]      = x0 * c0 - x1 * sn0;
        kpe[32 + j] = x1 * c1 + x0 * sn1;
    }
    __syncthreads();
    for (int idx = tid; idx < NH_ * QHD_; idx += blockDim.x) {
        int h = idx / QHD_, d = idx % QHD_;
        size_t dst = ((size_t)(b * NH_ + h) * S_ + s) * QHD_ + d;
        float qv;
        if (d < NOPE_) {
            qv = q[(size_t)t * (NH_ * QHD_) + h * QHD_ + d];
        } else {
            int j = d - NOPE_;
            int jj = (j < 32) ? j : j - 32;
            float x0 = q[(size_t)t * (NH_ * QHD_) + h * QHD_ + NOPE_ + 2 * jj];
            float x1 = q[(size_t)t * (NH_ * QHD_) + h * QHD_ + NOPE_ + 2 * jj + 1];
            float c = cosT[pos * ROPE_ + j], sn = sinT[pos * ROPE_ + j];
            qv = (j < 32) ? (x0 * c - x1 * sn) : (x1 * c + x0 * sn);
        }
        qh[dst] = qv;
        float kval = (d < NOPE_) ? kv[(size_t)t * (NH_ * 256) + h * 256 + d] : kpe[d - NOPE_];
        kh[dst] = kval;
    }
    for (int idx = tid; idx < NH_ * VD_; idx += blockDim.x) {
        int h = idx / VD_, d = idx % VD_;
        vh[((size_t)(b * NH_ + h) * S_ + s) * VD_ + d] =
            kv[(size_t)t * (NH_ * 256) + h * 256 + NOPE_ + d];
    }
}

// ---------------- scores = qh @ kh^T * SCALE (causal, lower blocks only) ----------------
__global__ void score_gemm_kernel(const float* __restrict__ qh, const float* __restrict__ kh,
                                  float* __restrict__ scores) {
    int bh = blockIdx.z;
    int bm = blockIdx.y, bn = blockIdx.x;
    if (bn > bm) return;  // fully masked block, never read
    const float* A = qh + (size_t)bh * S_ * QHD_;
    const float* Bq = kh + (size_t)bh * S_ * QHD_;
    __shared__ float As[BK][BM];
    __shared__ float Bs[BK][BN];
    int tid = threadIdx.x;
    int tx = tid & 15, ty = tid >> 4;
    int row0 = bm * BM, col0 = bn * BN;
    int a_row = tid >> 1, a_col = (tid & 1) * 4;
    float acc[TM][TN];
#pragma unroll
    for (int i = 0; i < TM; i++)
#pragma unroll
        for (int j = 0; j < TN; j++) acc[i][j] = 0.f;

    for (int k0 = 0; k0 < QHD_; k0 += BK) {
        float4 av = *(const float4*)&A[(size_t)(row0 + a_row) * QHD_ + k0 + a_col];
        As[a_col + 0][a_row] = av.x;
        As[a_col + 1][a_row] = av.y;
        As[a_col + 2][a_row] = av.z;
        As[a_col + 3][a_row] = av.w;
        float4 bv = *(const float4*)&Bq[(size_t)(col0 + a_row) * QHD_ + k0 + a_col];
        Bs[a_col + 0][a_row] = bv.x;
        Bs[a_col + 1][a_row] = bv.y;
        Bs[a_col + 2][a_row] = bv.z;
        Bs[a_col + 3][a_row] = bv.w;
        __syncthreads();
#pragma unroll
        for (int k = 0; k < BK; k++) {
            float ra[TM], rb[TN];
#pragma unroll
            for (int i = 0; i < TM; i++) ra[i] = As[k][ty * TM + i];
#pragma unroll
            for (int j = 0; j < TN; j++) rb[j] = Bs[k][tx * TN + j];
#pragma unroll
            for (int i = 0; i < TM; i++)
#pragma unroll
                for (int j = 0; j < TN; j++) acc[i][j] += ra[i] * rb[j];
        }
        __syncthreads();
    }
#pragma unroll
    for (int i = 0; i < TM; i++) {
        int r = row0 + ty * TM + i;
#pragma unroll
        for (int j = 0; j < TN; j++) {
            int c = col0 + tx * TN + j;
            if (c <= r)
                scores[((size_t)bh * S_ + r) * S_ + c] = acc[i][j] * SCALE_;
        }
    }
}

// ---------------- softmax (in place, causal length, padding mask) ----------------
__global__ void softmax_kernel(float* __restrict__ scores, const int* __restrict__ amask) {
    int row = blockIdx.x;               // b*NH*S + ...
    int i = row % S_;
    int bh = row / S_;
    int b = bh / NH_;
    float* p = scores + (size_t)row * S_;
    int len = i + 1;
    int tid = threadIdx.x;
    __shared__ float red[256];
    float m = -3.0e38f;
    for (int j = tid; j < len; j += 256) {
        float v = (amask[b * S_ + j] != 0) ? p[j] : -3.0e38f;
        m = fmaxf(m, v);
    }
    red[tid] = m; __syncthreads();
    for (int s = 128; s > 0; s >>= 1) { if (tid < s) red[tid] = fmaxf(red[tid], red[tid + s]); __syncthreads(); }
    m = red[0]; __syncthreads();
    float sum = 0.f;
    for (int j = tid; j < len; j += 256) {
        float v = (amask[b * S_ + j] != 0) ? p[j] : -3.0e38f;
        float e = expf(v - m);
        p[j] = e;
        sum += e;
    }
    red[tid] = sum; __syncthreads();
    for (int s = 128; s > 0; s >>= 1) { if (tid < s) red[tid] += red[tid + s]; __syncthreads(); }
    float inv = 1.f / red[0];
    for (int j = tid; j < len; j += 256) p[j] *= inv;
    for (int j = len + tid; j < S_; j += 256) p[j] = 0.f;
}

// ---------------- out = P @ V  (causal k-limit), scatter to (b,s,h*128+d) ----------------
__global__ void pv_gemm_kernel(const float* __restrict__ scores, const float* __restrict__ vh,
                               float* __restrict__ out) {
    int bh = blockIdx.z;
    int b = bh >> 4, h = bh & 15;
    int bm = blockIdx.y;
    const float* A = scores + (size_t)bh * S_ * S_;
    const float* Bv = vh + (size_t)bh * S_ * VD_;
    __shared__ float As[BK][BM];
    __shared__ float Bs[BK][BN];
    int tid = threadIdx.x;
    int tx = tid & 15, ty = tid >> 4;
    int row0 = bm * BM;
    int a_row = tid >> 1, a_col = (tid & 1) * 4;
    int b_row = tid >> 5, b_col = (tid & 31) * 4;
    float acc[TM][TN];
#pragma unroll
    for (int i = 0; i < TM; i++)
#pragma unroll
        for (int j = 0; j < TN; j++) acc[i][j] = 0.f;

    int kmax = row0 + BM;   // rows beyond this have zero attn weight (causal)
    for (int k0 = 0; k0 < kmax; k0 += BK) {
        float4 av = *(const float4*)&A[(size_t)(row0 + a_row) * S_ + k0 + a_col];
        As[a_col + 0][a_row] = av.x;
        As[a_col + 1][a_row] = av.y;
        As[a_col + 2][a_row] = av.z;
        As[a_col + 3][a_row] = av.w;
        float4 bv = *(const float4*)&Bv[(size_t)(k0 + b_row) * VD_ + b_col];
        *(float4*)&Bs[b_row][b_col] = bv;
        __syncthreads();
#pragma unroll
        for (int k = 0; k < BK; k++) {
            float ra[TM], rb[TN];
#pragma unroll
            for (int i = 0; i < TM; i++) ra[i] = As[k][ty * TM + i];
#pragma unroll
            for (int j = 0; j < TN; j++) rb[j] = Bs[k][tx * TN + j];
#pragma unroll
            for (int i = 0; i < TM; i++)
#pragma unroll
                for (int j = 0; j < TN; j++) acc[i][j] += ra[i] * rb[j];
        }
        __syncthreads();
    }
#pragma unroll
    for (int i = 0; i < TM; i++) {
        int r = row0 + ty * TM + i;
#pragma unroll
        for (int j = 0; j < TN; j += 4) {
            int c = tx * TN + j;
            float4 v = make_float4(acc[i][j], acc[i][j+1], acc[i][j+2], acc[i][j+3]);
            *(float4*)&out[(size_t)(b * S_ + r) * H_ + h * VD_ + c] = v;
        }
    }
}

// ---------------- launch ----------------
extern "C" void kernel_launch(void* const* d_in, const int* in_sizes, int n_in,
                              void* d_out, int out_size) {
    const float* hidden   = (const float*)d_in[0];
    const float* sinT     = (const float*)d_in[1];
    const float* cosT     = (const float*)d_in[2];
    const int*   pos_ids  = (const int*)  d_in[3];
    const int*   amask    = (const int*)  d_in[4];
    const float* in_ln_w  = (const float*)d_in[5];
    const float* q_a_w    = (const float*)d_in[6];
    const float* q_a_ln_w = (const float*)d_in[7];
    const float* q_b_w    = (const float*)d_in[8];
    const float* kv_a_w   = (const float*)d_in[9];
    const float* kv_a_ln_w= (const float*)d_in[10];
    const float* kv_b_w   = (const float*)d_in[11];
    const float* o_w      = (const float*)d_in[12];
    const float* post_ln_w= (const float*)d_in[13];
    const float* gate_w   = (const float*)d_in[14];
    const float* up_w     = (const float*)d_in[15];
    const float* down_w   = (const float*)d_in[16];
    float* outp = (float*)d_out;

    float *x, *qa, *q, *ckv, *ckvn, *kv, *qh, *kh, *vh, *scores, *attnout, *h1, *y, *gate, *act;
    cudaGetSymbolAddress((void**)&x, g_x);
    cudaGetSymbolAddress((void**)&qa, g_qa);
    cudaGetSymbolAddress((void**)&q, g_q);
    cudaGetSymbolAddress((void**)&ckv, g_ckv);
    cudaGetSymbolAddress((void**)&ckvn, g_ckvn);
    cudaGetSymbolAddress((void**)&kv, g_kv);
    cudaGetSymbolAddress((void**)&qh, g_qh);
    cudaGetSymbolAddress((void**)&kh, g_kh);
    cudaGetSymbolAddress((void**)&vh, g_vh);
    cudaGetSymbolAddress((void**)&scores, g_scores);
    cudaGetSymbolAddress((void**)&attnout, g_attnout);
    cudaGetSymbolAddress((void**)&h1, g_h1);
    cudaGetSymbolAddress((void**)&y, g_y);
    cudaGetSymbolAddress((void**)&gate, g_gate);
    cudaGetSymbolAddress((void**)&act, g_act);

    // 1. x = rms(hidden, in_ln_w)
    rms_kernel<<<T_, 256>>>(hidden, in_ln_w, x, H_, H_, H_);
    // 2. qa = x @ q_a_w
    gemm_kernel<0><<<dim3(QLR_/BN, T_/BM), 256>>>(x, q_a_w, qa, nullptr, T_, QLR_, H_);
    // 3. qa = rms(qa) in place
    rms_kernel<<<T_, 256>>>(qa, q_a_ln_w, qa, QLR_, QLR_, QLR_);
    // 4. q = qa @ q_b_w
    gemm_kernel<0><<<dim3(NH_*QHD_/BN, T_/BM), 256>>>(qa, q_b_w, q, nullptr, T_, NH_*QHD_, QLR_);
    // 5. ckv = x @ kv_a_w   (N = 576, partial tile)
    gemm_kernel<0><<<dim3((KVLR_+ROPE_+BN-1)/BN, T_/BM), 256>>>(x, kv_a_w, ckv, nullptr, T_, KVLR_+ROPE_, H_);
    // 6. ckvn = rms(ckv[:, :512])
    rms_kernel<<<T_, 256>>>(ckv, kv_a_ln_w, ckvn, KVLR_, KVLR_+ROPE_, KVLR_);
    // 7. kv = ckvn @ kv_b_w
    gemm_kernel<0><<<dim3(NH_*256/BN, T_/BM), 256>>>(ckvn, kv_b_w, kv, nullptr, T_, NH_*256, KVLR_);
    // 8. assemble per-head layouts + RoPE
    assemble_kernel<<<T_, 256>>>(q, kv, ckv, cosT, sinT, pos_ids, qh, kh, vh);
    // 9. scores (causal blocks only)
    score_gemm_kernel<<<dim3(S_/BN, S_/BM, B_*NH_), 256>>>(qh, kh, scores);
    // 10. softmax
    softmax_kernel<<<B_*NH_*S_, 256>>>(scores, amask);
    // 11. out = P @ V
    pv_gemm_kernel<<<dim3(1, S_/BM, B_*NH_), 256>>>(scores, vh, attnout);
    // 12. h1 = attnout @ o_w + hidden
    gemm_kernel<1><<<dim3(H_/BN, T_/BM), 256>>>(attnout, o_w, h1, hidden, T_, H_, H_);
    // 13. y = rms(h1, post_ln_w)
    rms_kernel<<<T_, 256>>>(h1, post_ln_w, y, H_, H_, H_);
    // 14. gate = y @ gate_w
    gemm_kernel<0><<<dim3(I_/BN, T_/BM), 256>>>(y, gate_w, gate, nullptr, T_, I_, H_);
    // 15. act = silu(gate) * (y @ up_w)
    gemm_kernel<2><<<dim3(I_/BN, T_/BM), 256>>>(y, up_w, act, gate, T_, I_, H_);
    // 16. out = act @ down_w + h1
    gemm_kernel<1><<<dim3(H_/BN, T_/BM), 256>>>(act, down_w, outp, h1, T_, H_, I_);
    (void)in_sizes; (void)n_in; (void)out_size;
}

// round 2
// speedup vs baseline: 3.1240x; 3.1240x over previous
#include <cuda_runtime.h>
#include <math.h>

// ---------------- problem constants ----------------
#define B_    2
#define S_    1024
#define H_    2048
#define NH_   16
#define QLR_  1536
#define KVLR_ 512
#define NOPE_ 128
#define ROPE_ 64
#define VD_   128
#define QHD_  192
#define I_    8192
#define T_    (B_*S_)
#define SCALE_ 0.07216878364870323f
#define EPS_  1e-6f

// ---------------- scratch ----------------
__device__ float g_x[T_ * H_];
__device__ float g_qa[T_ * QLR_];
__device__ float g_q[T_ * NH_ * QHD_];
__device__ float g_ckv[T_ * (KVLR_ + ROPE_)];
__device__ float g_ckvn[T_ * KVLR_];
__device__ float g_kv[T_ * NH_ * (NOPE_ + VD_)];
__device__ float g_qh[(size_t)B_ * NH_ * S_ * QHD_];
__device__ float g_kh[(size_t)B_ * NH_ * S_ * QHD_];
__device__ float g_vh[(size_t)B_ * NH_ * S_ * VD_];
__device__ float g_scores[(size_t)B_ * NH_ * S_ * S_];
__device__ float g_attnout[T_ * H_];
__device__ float g_h1[T_ * H_];
__device__ float g_y[T_ * H_];
__device__ float g_gate[(size_t)T_ * I_];
__device__ float g_act[(size_t)T_ * I_];

__device__ __forceinline__ unsigned f2tf(float x) {
    unsigned u; asm("cvt.rna.tf32.f32 %0, %1;" : "=r"(u) : "f"(x)); return u;
}

#define MMA_TF32(C, A, B) \
    asm volatile("mma.sync.aligned.m16n8k8.row.col.f32.tf32.tf32.f32 " \
        "{%0,%1,%2,%3},{%4,%5,%6,%7},{%8,%9},{%0,%1,%2,%3};" \
        : "+f"((C)[0]), "+f"((C)[1]), "+f"((C)[2]), "+f"((C)[3]) \
        : "r"((A)[0]), "r"((A)[1]), "r"((A)[2]), "r"((A)[3]), "r"((B)[0]), "r"((B)[1]))

// smem strides: pad to 136 (136 % 32 == 8) -> fragment loads conflict-free
#define SA 136
#define SB 136

// ================= generic tf32 GEMM: C(MxN) = A(MxK) @ B(KxN) =================
// EPI: 0 store, 1 acc + R, 2 silu(R)*acc
template<int EPI>
__global__ __launch_bounds__(256) void gemm_mma(
    const float* __restrict__ A, const float* __restrict__ Bm,
    float* __restrict__ C, const float* __restrict__ R, int M, int N, int K) {
    __shared__ unsigned As[2][16][SA];
    __shared__ unsigned Bs[2][16][SB];
    int t = threadIdx.x, lane = t & 31, w = t >> 5;
    int wm = w & 3, wn = w >> 2;       // 4 warps M, 2 warps N
    int row0 = blockIdx.y * 128, col0 = blockIdx.x * 128;
    int grp = lane >> 2, tig = lane & 3;

    float acc[2][8][4];
#pragma unroll
    for (int mt = 0; mt < 2; mt++)
#pragma unroll
        for (int nt = 0; nt < 8; nt++)
#pragma unroll
            for (int i = 0; i < 4; i++) acc[mt][nt][i] = 0.f;

    int KT = K >> 4;
    float4 ar[2], br[2];

    auto load = [&](int kt) {
        int k0 = kt << 4;
#pragma unroll
        for (int i = 0; i < 2; i++) {
            int idx = i * 256 + t;
            int m = idx >> 2, c4 = (idx & 3) << 2;
            ar[i] = *(const float4*)&A[(size_t)(row0 + m) * K + k0 + c4];
            int kr = idx >> 5, n4 = (idx & 31) << 2;
            int gc = col0 + n4;
            br[i] = (gc < N) ? *(const float4*)&Bm[(size_t)(k0 + kr) * N + gc]
                             : make_float4(0.f, 0.f, 0.f, 0.f);
        }
    };
    auto stor = [&](int buf) {
#pragma unroll
        for (int i = 0; i < 2; i++) {
            int idx = i * 256 + t;
            int m = idx >> 2, c4 = (idx & 3) << 2;
            As[buf][c4 + 0][m] = f2tf(ar[i].x);
            As[buf][c4 + 1][m] = f2tf(ar[i].y);
            As[buf][c4 + 2][m] = f2tf(ar[i].z);
            As[buf][c4 + 3][m] = f2tf(ar[i].w);
            int kr = idx >> 5, n4 = (idx & 31) << 2;
            Bs[buf][kr][n4 + 0] = f2tf(br[i].x);
            Bs[buf][kr][n4 + 1] = f2tf(br[i].y);
            Bs[buf][kr][n4 + 2] = f2tf(br[i].z);
            Bs[buf][kr][n4 + 3] = f2tf(br[i].w);
        }
    };

    load(0); stor(0); __syncthreads();
    int buf = 0;
    for (int kt = 0; kt < KT; kt++) {
        if (kt + 1 < KT) load(kt + 1);
#pragma unroll
        for (int kk = 0; kk < 16; kk += 8) {
            unsigned af[2][4], bf[8][2];
#pragma unroll
            for (int mt = 0; mt < 2; mt++) {
                int mr = wm * 32 + mt * 16 + grp;
                af[mt][0] = As[buf][kk + tig][mr];
                af[mt][1] = As[buf][kk + tig][mr + 8];
                af[mt][2] = As[buf][kk + tig + 4][mr];
                af[mt][3] = As[buf][kk + tig + 4][mr + 8];
            }
#pragma unroll
            for (int nt = 0; nt < 8; nt++) {
                int nc = wn * 64 + nt * 8 + grp;
                bf[nt][0] = Bs[buf][kk + tig][nc];
                bf[nt][1] = Bs[buf][kk + tig + 4][nc];
            }
#pragma unroll
            for (int mt = 0; mt < 2; mt++)
#pragma unroll
                for (int nt = 0; nt < 8; nt++) MMA_TF32(acc[mt][nt], af[mt], bf[nt]);
        }
        if (kt + 1 < KT) stor(buf ^ 1);
        __syncthreads();
        buf ^= 1;
    }
#pragma unroll
    for (int mt = 0; mt < 2; mt++)
#pragma unroll
        for (int h = 0; h < 2; h++) {
            int r = row0 + wm * 32 + mt * 16 + grp + h * 8;
#pragma unroll
            for (int nt = 0; nt < 8; nt++) {
                int c = col0 + wn * 64 + nt * 8 + tig * 2;
                if (c < N) {
                    float vx = acc[mt][nt][h * 2], vy = acc[mt][nt][h * 2 + 1];
                    if (EPI == 1) {
                        float2 rr = *(const float2*)&R[(size_t)r * N + c];
                        vx += rr.x; vy += rr.y;
                    } else if (EPI == 2) {
                        float2 rr = *(const float2*)&R[(size_t)r * N + c];
                        vx *= rr.x / (1.f + __expf(-rr.x));
                        vy *= rr.y / (1.f + __expf(-rr.y));
                    }
                    *(float2*)&C[(size_t)r * N + c] = make_float2(vx, vy);
                }
            }
        }
}

// ================= scores = qh @ kh^T * SCALE (causal blocks) =================
__global__ __launch_bounds__(256) void score_mma(
    const float* __restrict__ qh, const float* __restrict__ kh,
    float* __restrict__ scores) {
    int bm = blockIdx.y, bn = blockIdx.x;
    if (bn > bm) return;
    int bh = blockIdx.z;
    const float* Aq = qh + (size_t)bh * S_ * QHD_;
    const float* Bk = kh + (size_t)bh * S_ * QHD_;
    __shared__ unsigned As[2][16][SA];
    __shared__ unsigned Bs[2][16][SB];
    int t = threadIdx.x, lane = t & 31, w = t >> 5;
    int wm = w & 3, wn = w >> 2;
    int row0 = bm * 128, col0 = bn * 128;
    int grp = lane >> 2, tig = lane & 3;

    float acc[2][8][4];
#pragma unroll
    for (int mt = 0; mt < 2; mt++)
#pragma unroll
        for (int nt = 0; nt < 8; nt++)
#pragma unroll
            for (int i = 0; i < 4; i++) acc[mt][nt][i] = 0.f;

    float4 ar[2], br[2];
    auto load = [&](int kt) {
        int k0 = kt << 4;
#pragma unroll
        for (int i = 0; i < 2; i++) {
            int idx = i * 256 + t;
            int m = idx >> 2, c4 = (idx & 3) << 2;
            ar[i] = *(const float4*)&Aq[(size_t)(row0 + m) * QHD_ + k0 + c4];
            br[i] = *(const float4*)&Bk[(size_t)(col0 + m) * QHD_ + k0 + c4];
        }
    };
    auto stor = [&](int buf) {
#pragma unroll
        for (int i = 0; i < 2; i++) {
            int idx = i * 256 + t;
            int m = idx >> 2, c4 = (idx & 3) << 2;
            As[buf][c4 + 0][m] = f2tf(ar[i].x);
            As[buf][c4 + 1][m] = f2tf(ar[i].y);
            As[buf][c4 + 2][m] = f2tf(ar[i].z);
            As[buf][c4 + 3][m] = f2tf(ar[i].w);
            Bs[buf][c4 + 0][m] = f2tf(br[i].x);
            Bs[buf][c4 + 1][m] = f2tf(br[i].y);
            Bs[buf][c4 + 2][m] = f2tf(br[i].z);
            Bs[buf][c4 + 3][m] = f2tf(br[i].w);
        }
    };

    const int KT = QHD_ / 16;  // 12
    load(0); stor(0); __syncthreads();
    int buf = 0;
    for (int kt = 0; kt < KT; kt++) {
        if (kt + 1 < KT) load(kt + 1);
#pragma unroll
        for (int kk = 0; kk < 16; kk += 8) {
            unsigned af[2][4], bf[8][2];
#pragma unroll
            for (int mt = 0; mt < 2; mt++) {
                int mr = wm * 32 + mt * 16 + grp;
                af[mt][0] = As[buf][kk + tig][mr];
                af[mt][1] = As[buf][kk + tig][mr + 8];
                af[mt][2] = As[buf][kk + tig + 4][mr];
                af[mt][3] = As[buf][kk + tig + 4][mr + 8];
            }
#pragma unroll
            for (int nt = 0; nt < 8; nt++) {
                int nc = wn * 64 + nt * 8 + grp;
                bf[nt][0] = Bs[buf][kk + tig][nc];
                bf[nt][1] = Bs[buf][kk + tig + 4][nc];
            }
#pragma unroll
            for (int mt = 0; mt < 2; mt++)
#pragma unroll
                for (int nt = 0; nt < 8; nt++) MMA_TF32(acc[mt][nt], af[mt], bf[nt]);
        }
        if (kt + 1 < KT) stor(buf ^ 1);
        __syncthreads();
        buf ^= 1;
    }
    float* out = scores + (size_t)bh * S_ * S_;
#pragma unroll
    for (int mt = 0; mt < 2; mt++)
#pragma unroll
        for (int h = 0; h < 2; h++) {
            int r = row0 + wm * 32 + mt * 16 + grp + h * 8;
#pragma unroll
            for (int nt = 0; nt < 8; nt++) {
                int c = col0 + wn * 64 + nt * 8 + tig * 2;
                if (c     <= r) out[(size_t)r * S_ + c]     = acc[mt][nt][h * 2]     * SCALE_;
                if (c + 1 <= r) out[(size_t)r * S_ + c + 1] = acc[mt][nt][h * 2 + 1] * SCALE_;
            }
        }
}

// ================= out = P @ V (causal k-limit) =================
__global__ __launch_bounds__(256) void pv_mma(
    const float* __restrict__ scores, const float* __restrict__ vh,
    float* __restrict__ out) {
    int bh = blockIdx.z;
    int b = bh >> 4, hd = bh & 15;
    int bm = blockIdx.y;
    const float* Ap = scores + (size_t)bh * S_ * S_;
    const float* Bv = vh + (size_t)bh * S_ * VD_;
    __shared__ unsigned As[2][16][SA];
    __shared__ unsigned Bs[2][16][SB];
    int t = threadIdx.x, lane = t & 31, w = t >> 5;
    int wm = w & 3, wn = w >> 2;
    int row0 = bm * 128;
    int grp = lane >> 2, tig = lane & 3;

    float acc[2][8][4];
#pragma unroll
    for (int mt = 0; mt < 2; mt++)
#pragma unroll
        for (int nt = 0; nt < 8; nt++)
#pragma unroll
            for (int i = 0; i < 4; i++) acc[mt][nt][i] = 0.f;

    float4 ar[2], br[2];
    auto load = [&](int kt) {
        int k0 = kt << 4;
#pragma unroll
        for (int i = 0; i < 2; i++) {
            int idx = i * 256 + t;
            int m = idx >> 2, c4 = (idx & 3) << 2;
            ar[i] = *(const float4*)&Ap[(size_t)(row0 + m) * S_ + k0 + c4];
            int kr = idx >> 5, n4 = (idx & 31) << 2;
            br[i] = *(const float4*)&Bv[(size_t)(k0 + kr) * VD_ + n4];
        }
    };
    auto stor = [&](int buf) {
#pragma unroll
        for (int i = 0; i < 2; i++) {
            int idx = i * 256 + t;
            int m = idx >> 2, c4 = (idx & 3) << 2;
            As[buf][c4 + 0][m] = f2tf(ar[i].x);
            As[buf][c4 + 1][m] = f2tf(ar[i].y);
            As[buf][c4 + 2][m] = f2tf(ar[i].z);
            As[buf][c4 + 3][m] = f2tf(ar[i].w);
            int kr = idx >> 5, n4 = (idx & 31) << 2;
            Bs[buf][kr][n4 + 0] = f2tf(br[i].x);
            Bs[buf][kr][n4 + 1] = f2tf(br[i].y);
            Bs[buf][kr][n4 + 2] = f2tf(br[i].z);
            Bs[buf][kr][n4 + 3] = f2tf(br[i].w);
        }
    };

    int KT = (bm + 1) * 8;   // (row0+128)/16
    load(0); stor(0); __syncthreads();
    int buf = 0;
    for (int kt = 0; kt < KT; kt++) {
        if (kt + 1 < KT) load(kt + 1);
#pragma unroll
        for (int kk = 0; kk < 16; kk += 8) {
            unsigned af[2][4], bf[8][2];
#pragma unroll
            for (int mt = 0; mt < 2; mt++) {
                int mr = wm * 32 + mt * 16 + grp;
                af[mt][0] = As[buf][kk + tig][mr];
                af[mt][1] = As[buf][kk + tig][mr + 8];
                af[mt][2] = As[buf][kk + tig + 4][mr];
                af[mt][3] = As[buf][kk + tig + 4][mr + 8];
            }
#pragma unroll
            for (int nt = 0; nt < 8; nt++) {
                int nc = wn * 64 + nt * 8 + grp;
                bf[nt][0] = Bs[buf][kk + tig][nc];
                bf[nt][1] = Bs[buf][kk + tig + 4][nc];
            }
#pragma unroll
            for (int mt = 0; mt < 2; mt++)
#pragma unroll
                for (int nt = 0; nt < 8; nt++) MMA_TF32(acc[mt][nt], af[mt], bf[nt]);
        }
        if (kt + 1 < KT) stor(buf ^ 1);
        __syncthreads();
        buf ^= 1;
    }
#pragma unroll
    for (int mt = 0; mt < 2; mt++)
#pragma unroll
        for (int h = 0; h < 2; h++) {
            int r = row0 + wm * 32 + mt * 16 + grp + h * 8;
#pragma unroll
            for (int nt = 0; nt < 8; nt++) {
                int c = wn * 64 + nt * 8 + tig * 2;
                *(float2*)&out[(size_t)(b * S_ + r) * H_ + hd * VD_ + c] =
                    make_float2(acc[mt][nt][h * 2], acc[mt][nt][h * 2 + 1]);
            }
        }
}

// ---------------- rmsnorm ----------------
__global__ void rms_kernel(const float* __restrict__ in, const float* __restrict__ w,
                           float* __restrict__ out, int D, int in_stride, int out_stride) {
    int tk = blockIdx.x;
    const float* x = in + (size_t)tk * in_stride;
    float* y = out + (size_t)tk * out_stride;
    int tid = threadIdx.x;
    float ss = 0.f;
    for (int j = tid; j < D; j += blockDim.x) { float v = x[j]; ss += v * v; }
    __shared__ float red[256];
    red[tid] = ss; __syncthreads();
    for (int s = 128; s > 0; s >>= 1) { if (tid < s) red[tid] += red[tid + s]; __syncthreads(); }
    float scale = rsqrtf(red[0] / (float)D + EPS_);
    for (int j = tid; j < D; j += blockDim.x) y[j] = x[j] * scale * w[j];
}

// ---------------- assemble + RoPE ----------------
__global__ void assemble_kernel(const float* __restrict__ q, const float* __restrict__ kv,
                                const float* __restrict__ ckv,
                                const float* __restrict__ cosT, const float* __restrict__ sinT,
                                const int* __restrict__ pos_ids,
                                float* __restrict__ qh, float* __restrict__ kh,
                                float* __restrict__ vh) {
    int tk = blockIdx.x;
    int b = tk / S_, s = tk % S_;
    int tid = threadIdx.x;
    int pos = pos_ids[tk];
    __shared__ float kpe[ROPE_];
    if (tid < 32) {
        int j = tid;
        float x0 = ckv[(size_t)tk * (KVLR_ + ROPE_) + KVLR_ + 2 * j];
        float x1 = ckv[(size_t)tk * (KVLR_ + ROPE_) + KVLR_ + 2 * j + 1];
        float c0 = cosT[pos * ROPE_ + j],      sn0 = sinT[pos * ROPE_ + j];
        float c1 = cosT[pos * ROPE_ + 32 + j], sn1 = sinT[pos * ROPE_ + 32 + j];
        kpe[j]      = x0 * c0 - x1 * sn0;
        kpe[32 + j] = x1 * c1 + x0 * sn1;
    }
    __syncthreads();
    for (int idx = tid; idx < NH_ * QHD_; idx += blockDim.x) {
        int h = idx / QHD_, d = idx % QHD_;
        size_t dst = ((size_t)(b * NH_ + h) * S_ + s) * QHD_ + d;
        float qv;
        if (d < NOPE_) {
            qv = q[(size_t)tk * (NH_ * QHD_) + h * QHD_ + d];
        } else {
            int j = d - NOPE_;
            int jj = (j < 32) ? j : j - 32;
            float x0 = q[(size_t)tk * (NH_ * QHD_) + h * QHD_ + NOPE_ + 2 * jj];
            float x1 = q[(size_t)tk * (NH_ * QHD_) + h * QHD_ + NOPE_ + 2 * jj + 1];
            float c = cosT[pos * ROPE_ + j], sn = sinT[pos * ROPE_ + j];
            qv = (j < 32) ? (x0 * c - x1 * sn) : (x1 * c + x0 * sn);
        }
        qh[dst] = qv;
        float kval = (d < NOPE_) ? kv[(size_t)tk * (NH_ * 256) + h * 256 + d] : kpe[d - NOPE_];
        kh[dst] = kval;
    }
    for (int idx = tid; idx < NH_ * VD_; idx += blockDim.x) {
        int h = idx / VD_, d = idx % VD_;
        vh[((size_t)(b * NH_ + h) * S_ + s) * VD_ + d] =
            kv[(size_t)tk * (NH_ * 256) + h * 256 + NOPE_ + d];
    }
}

// ---------------- softmax ----------------
__global__ void softmax_kernel(float* __restrict__ scores, const int* __restrict__ amask) {
    int row = blockIdx.x;
    int i = row % S_;
    int bh = row / S_;
    int b = bh / NH_;
    float* p = scores + (size_t)row * S_;
    int len = i + 1;
    int tid = threadIdx.x;
    __shared__ float red[256];
    float m = -3.0e38f;
    for (int j = tid; j < len; j += 256) {
        float v = (amask[b * S_ + j] != 0) ? p[j] : -3.0e38f;
        m = fmaxf(m, v);
    }
    red[tid] = m; __syncthreads();
    for (int s = 128; s > 0; s >>= 1) { if (tid < s) red[tid] = fmaxf(red[tid], red[tid + s]); __syncthreads(); }
    m = red[0]; __syncthreads();
    float sum = 0.f;
    for (int j = tid; j < len; j += 256) {
        float v = (amask[b * S_ + j] != 0) ? p[j] : -3.0e38f;
        float e = expf(v - m);
        p[j] = e;
        sum += e;
    }
    red[tid] = sum; __syncthreads();
    for (int s = 128; s > 0; s >>= 1) { if (tid < s) red[tid] += red[tid + s]; __syncthreads(); }
    float inv = 1.f / red[0];
    for (int j = tid; j < len; j += 256) p[j] *= inv;
    for (int j = len + tid; j < S_; j += 256) p[j] = 0.f;
}

// ---------------- launch ----------------
extern "C" void kernel_launch(void* const* d_in, const int* in_sizes, int n_in,
                              void* d_out, int out_size) {
    const float* hidden   = (const float*)d_in[0];
    const float* sinT     = (const float*)d_in[1];
    const float* cosT     = (const float*)d_in[2];
    const int*   pos_ids  = (const int*)  d_in[3];
    const int*   amask    = (const int*)  d_in[4];
    const float* in_ln_w  = (const float*)d_in[5];
    const float* q_a_w    = (const float*)d_in[6];
    const float* q_a_ln_w = (const float*)d_in[7];
    const float* q_b_w    = (const float*)d_in[8];
    const float* kv_a_w   = (const float*)d_in[9];
    const float* kv_a_ln_w= (const float*)d_in[10];
    const float* kv_b_w   = (const float*)d_in[11];
    const float* o_w      = (const float*)d_in[12];
    const float* post_ln_w= (const float*)d_in[13];
    const float* gate_w   = (const float*)d_in[14];
    const float* up_w     = (const float*)d_in[15];
    const float* down_w   = (const float*)d_in[16];
    float* outp = (float*)d_out;

    float *x, *qa, *q, *ckv, *ckvn, *kv, *qh, *kh, *vh, *scores, *attnout, *h1, *y, *gate, *act;
    cudaGetSymbolAddress((void**)&x, g_x);
    cudaGetSymbolAddress((void**)&qa, g_qa);
    cudaGetSymbolAddress((void**)&q, g_q);
    cudaGetSymbolAddress((void**)&ckv, g_ckv);
    cudaGetSymbolAddress((void**)&ckvn, g_ckvn);
    cudaGetSymbolAddress((void**)&kv, g_kv);
    cudaGetSymbolAddress((void**)&qh, g_qh);
    cudaGetSymbolAddress((void**)&kh, g_kh);
    cudaGetSymbolAddress((void**)&vh, g_vh);
    cudaGetSymbolAddress((void**)&scores, g_scores);
    cudaGetSymbolAddress((void**)&attnout, g_attnout);
    cudaGetSymbolAddress((void**)&h1, g_h1);
    cudaGetSymbolAddress((void**)&y, g_y);
    cudaGetSymbolAddress((void**)&gate, g_gate);
    cudaGetSymbolAddress((void**)&act, g_act);

    rms_kernel<<<T_, 256>>>(hidden, in_ln_w, x, H_, H_, H_);
    gemm_mma<0><<<dim3(QLR_/128, T_/128), 256>>>(x, q_a_w, qa, nullptr, T_, QLR_, H_);
    rms_kernel<<<T_, 256>>>(qa, q_a_ln_w, qa, QLR_, QLR_, QLR_);
    gemm_mma<0><<<dim3(NH_*QHD_/128, T_/128), 256>>>(qa, q_b_w, q, nullptr, T_, NH_*QHD_, QLR_);
    gemm_mma<0><<<dim3((KVLR_+ROPE_+127)/128, T_/128), 256>>>(x, kv_a_w, ckv, nullptr, T_, KVLR_+ROPE_, H_);
    rms_kernel<<<T_, 256>>>(ckv, kv_a_ln_w, ckvn, KVLR_, KVLR_+ROPE_, KVLR_);
    gemm_mma<0><<<dim3(NH_*256/128, T_/128), 256>>>(ckvn, kv_b_w, kv, nullptr, T_, NH_*256, KVLR_);
    assemble_kernel<<<T_, 256>>>(q, kv, ckv, cosT, sinT, pos_ids, qh, kh, vh);
    score_mma<<<dim3(S_/128, S_/128, B_*NH_), 256>>>(qh, kh, scores);
    softmax_kernel<<<B_*NH_*S_, 256>>>(scores, amask);
    pv_mma<<<dim3(1, S_/128, B_*NH_), 256>>>(scores, vh, attnout);
    gemm_mma<1><<<dim3(H_/128, T_/128), 256>>>(attnout, o_w, h1, hidden, T_, H_, H_);
    rms_kernel<<<T_, 256>>>(h1, post_ln_w, y, H_, H_, H_);
    gemm_mma<0><<<dim3(I_/128, T_/128), 256>>>(y, gate_w, gate, nullptr, T_, I_, H_);
    gemm_mma<2><<<dim3(I_/128, T_/128), 256>>>(y, up_w, act, gate, T_, I_, H_);
    gemm_mma<1><<<dim3(H_/128, T_/128), 256>>>(act, down_w, outp, h1, T_, H_, I_);
    (void)in_sizes; (void)n_in; (void)out_size;
}

// round 3
// speedup vs baseline: 3.1271x; 1.0010x over previous
#include <cuda_runtime.h>
#include <math.h>

// ---------------- problem constants ----------------
#define B_    2
#define S_    1024
#define H_    2048
#define NH_   16
#define QLR_  1536
#define KVLR_ 512
#define NOPE_ 128
#define ROPE_ 64
#define VD_   128
#define QHD_  192
#define I_    8192
#define T_    (B_*S_)
#define SCALE_ 0.07216878364870323f
#define EPS_  1e-6f

// ---------------- scratch ----------------
__device__ float g_x[T_ * H_];
__device__ float g_qa[T_ * QLR_];
__device__ float g_q[T_ * NH_ * QHD_];
__device__ float g_ckv[T_ * (KVLR_ + ROPE_)];
__device__ float g_ckvn[T_ * KVLR_];
__device__ float g_kv[T_ * NH_ * (NOPE_ + VD_)];
__device__ float g_qh[(size_t)B_ * NH_ * S_ * QHD_];
__device__ float g_kh[(size_t)B_ * NH_ * S_ * QHD_];
__device__ float g_vh[(size_t)B_ * NH_ * S_ * VD_];
__device__ float g_scores[(size_t)B_ * NH_ * S_ * S_];
__device__ float g_attnout[T_ * H_];
__device__ float g_h1[T_ * H_];
__device__ float g_y[T_ * H_];
__device__ float g_gate[(size_t)T_ * I_];
__device__ float g_act[(size_t)T_ * I_];

__device__ __forceinline__ unsigned f2tf(float x) {
    unsigned u; asm("cvt.rna.tf32.f32 %0, %1;" : "=r"(u) : "f"(x)); return u;
}

#define MMA_TF32(C, A, B) \
    asm volatile("mma.sync.aligned.m16n8k8.row.col.f32.tf32.tf32.f32 " \
        "{%0,%1,%2,%3},{%4,%5,%6,%7},{%8,%9},{%0,%1,%2,%3};" \
        : "+f"((C)[0]), "+f"((C)[1]), "+f"((C)[2]), "+f"((C)[3]) \
        : "r"((A)[0]), "r"((A)[1]), "r"((A)[2]), "r"((A)[3]), "r"((B)[0]), "r"((B)[1]))

// smem strides: pad to 136 (136 % 32 == 8) -> fragment loads conflict-free
#define SA 136
#define SB 136

// ================= generic tf32 GEMM: C(MxN) = A(MxK) @ B(KxN) =================
// EPI: 0 store, 1 acc + R, 2 silu(R)*acc
template<int EPI>
__global__ __launch_bounds__(256) void gemm_mma(
    const float* __restrict__ A, const float* __restrict__ Bm,
    float* __restrict__ C, const float* __restrict__ R, int M, int N, int K) {
    __shared__ unsigned As[2][16][SA];
    __shared__ unsigned Bs[2][16][SB];
    int t = threadIdx.x, lane = t & 31, w = t >> 5;
    int wm = w & 3, wn = w >> 2;       // 4 warps M, 2 warps N
    int row0 = blockIdx.y * 128, col0 = blockIdx.x * 128;
    int grp = lane >> 2, tig = lane & 3;

    float acc[2][8][4];
#pragma unroll
    for (int mt = 0; mt < 2; mt++)
#pragma unroll
        for (int nt = 0; nt < 8; nt++)
#pragma unroll
            for (int i = 0; i < 4; i++) acc[mt][nt][i] = 0.f;

    int KT = K >> 4;
    float4 ar[2], br[2];

    auto load = [&](int kt) {
        int k0 = kt << 4;
#pragma unroll
        for (int i = 0; i < 2; i++) {
            int idx = i * 256 + t;
            int m = idx >> 2, c4 = (idx & 3) << 2;
            ar[i] = *(const float4*)&A[(size_t)(row0 + m) * K + k0 + c4];
            int kr = idx >> 5, n4 = (idx & 31) << 2;
            int gc = col0 + n4;
            br[i] = (gc < N) ? *(const float4*)&Bm[(size_t)(k0 + kr) * N + gc]
                             : make_float4(0.f, 0.f, 0.f, 0.f);
        }
    };
    auto stor = [&](int buf) {
#pragma unroll
        for (int i = 0; i < 2; i++) {
            int idx = i * 256 + t;
            int m = idx >> 2, c4 = (idx & 3) << 2;
            As[buf][c4 + 0][m] = f2tf(ar[i].x);
            As[buf][c4 + 1][m] = f2tf(ar[i].y);
            As[buf][c4 + 2][m] = f2tf(ar[i].z);
            As[buf][c4 + 3][m] = f2tf(ar[i].w);
            int kr = idx >> 5, n4 = (idx & 31) << 2;
            Bs[buf][kr][n4 + 0] = f2tf(br[i].x);
            Bs[buf][kr][n4 + 1] = f2tf(br[i].y);
            Bs[buf][kr][n4 + 2] = f2tf(br[i].z);
            Bs[buf][kr][n4 + 3] = f2tf(br[i].w);
        }
    };

    load(0); stor(0); __syncthreads();
    int buf = 0;
    for (int kt = 0; kt < KT; kt++) {
        if (kt + 1 < KT) load(kt + 1);
#pragma unroll
        for (int kk = 0; kk < 16; kk += 8) {
            unsigned af[2][4], bf[8][2];
#pragma unroll
            for (int mt = 0; mt < 2; mt++) {
                int mr = wm * 32 + mt * 16 + grp;
                af[mt][0] = As[buf][kk + tig][mr];
                af[mt][1] = As[buf][kk + tig][mr + 8];
                af[mt][2] = As[buf][kk + tig + 4][mr];
                af[mt][3] = As[buf][kk + tig + 4][mr + 8];
            }
#pragma unroll
            for (int nt = 0; nt < 8; nt++) {
                int nc = wn * 64 + nt * 8 + grp;
                bf[nt][0] = Bs[buf][kk + tig][nc];
                bf[nt][1] = Bs[buf][kk + tig + 4][nc];
            }
#pragma unroll
            for (int mt = 0; mt < 2; mt++)
#pragma unroll
                for (int nt = 0; nt < 8; nt++) MMA_TF32(acc[mt][nt], af[mt], bf[nt]);
        }
        if (kt + 1 < KT) stor(buf ^ 1);
        __syncthreads();
        buf ^= 1;
    }
#pragma unroll
    for (int mt = 0; mt < 2; mt++)
#pragma unroll
        for (int h = 0; h < 2; h++) {
            int r = row0 + wm * 32 + mt * 16 + grp + h * 8;
#pragma unroll
            for (int nt = 0; nt < 8; nt++) {
                int c = col0 + wn * 64 + nt * 8 + tig * 2;
                if (c < N) {
                    float vx = acc[mt][nt][h * 2], vy = acc[mt][nt][h * 2 + 1];
                    if (EPI == 1) {
                        float2 rr = *(const float2*)&R[(size_t)r * N + c];
                        vx += rr.x; vy += rr.y;
                    } else if (EPI == 2) {
                        float2 rr = *(const float2*)&R[(size_t)r * N + c];
                        vx *= rr.x / (1.f + __expf(-rr.x));
                        vy *= rr.y / (1.f + __expf(-rr.y));
                    }
                    *(float2*)&C[(size_t)r * N + c] = make_float2(vx, vy);
                }
            }
        }
}

// ================= scores = qh @ kh^T * SCALE (causal blocks) =================
__global__ __launch_bounds__(256) void score_mma(
    const float* __restrict__ qh, const float* __restrict__ kh,
    float* __restrict__ scores) {
    int bm = blockIdx.y, bn = blockIdx.x;
    if (bn > bm) return;
    int bh = blockIdx.z;
    const float* Aq = qh + (size_t)bh * S_ * QHD_;
    const float* Bk = kh + (size_t)bh * S_ * QHD_;
    __shared__ unsigned As[2][16][SA];
    __shared__ unsigned Bs[2][16][SB];
    int t = threadIdx.x, lane = t & 31, w = t >> 5;
    int wm = w & 3, wn = w >> 2;
    int row0 = bm * 128, col0 = bn * 128;
    int grp = lane >> 2, tig = lane & 3;

    float acc[2][8][4];
#pragma unroll
    for (int mt = 0; mt < 2; mt++)
#pragma unroll
        for (int nt = 0; nt < 8; nt++)
#pragma unroll
            for (int i = 0; i < 4; i++) acc[mt][nt][i] = 0.f;

    float4 ar[2], br[2];
    auto load = [&](int kt) {
        int k0 = kt << 4;
#pragma unroll
        for (int i = 0; i < 2; i++) {
            int idx = i * 256 + t;
            int m = idx >> 2, c4 = (idx & 3) << 2;
            ar[i] = *(const float4*)&Aq[(size_t)(row0 + m) * QHD_ + k0 + c4];
            br[i] = *(const float4*)&Bk[(size_t)(col0 + m) * QHD_ + k0 + c4];
        }
    };
    auto stor = [&](int buf) {
#pragma unroll
        for (int i = 0; i < 2; i++) {
            int idx = i * 256 + t;
            int m = idx >> 2, c4 = (idx & 3) << 2;
            As[buf][c4 + 0][m] = f2tf(ar[i].x);
            As[buf][c4 + 1][m] = f2tf(ar[i].y);
            As[buf][c4 + 2][m] = f2tf(ar[i].z);
            As[buf][c4 + 3][m] = f2tf(ar[i].w);
            Bs[buf][c4 + 0][m] = f2tf(br[i].x);
            Bs[buf][c4 + 1][m] = f2tf(br[i].y);
            Bs[buf][c4 + 2][m] = f2tf(br[i].z);
            Bs[buf][c4 + 3][m] = f2tf(br[i].w);
        }
    };

    const int KT = QHD_ / 16;  // 12
    load(0); stor(0); __syncthreads();
    int buf = 0;
    for (int kt = 0; kt < KT; kt++) {
        if (kt + 1 < KT) load(kt + 1);
#pragma unroll
        for (int kk = 0; kk < 16; kk += 8) {
            unsigned af[2][4], bf[8][2];
#pragma unroll
            for (int mt = 0; mt < 2; mt++) {
                int mr = wm * 32 + mt * 16 + grp;
                af[mt][0] = As[buf][kk + tig][mr];
                af[mt][1] = As[buf][kk + tig][mr + 8];
                af[mt][2] = As[buf][kk + tig + 4][mr];
                af[mt][3] = As[buf][kk + tig + 4][mr + 8];
            }
#pragma unroll
            for (int nt = 0; nt < 8; nt++) {
                int nc = wn * 64 + nt * 8 + grp;
                bf[nt][0] = Bs[buf][kk + tig][nc];
                bf[nt][1] = Bs[buf][kk + tig + 4][nc];
            }
#pragma unroll
            for (int mt = 0; mt < 2; mt++)
#pragma unroll
                for (int nt = 0; nt < 8; nt++) MMA_TF32(acc[mt][nt], af[mt], bf[nt]);
        }
        if (kt + 1 < KT) stor(buf ^ 1);
        __syncthreads();
        buf ^= 1;
    }
    float* out = scores + (size_t)bh * S_ * S_;
#pragma unroll
    for (int mt = 0; mt < 2; mt++)
#pragma unroll
        for (int h = 0; h < 2; h++) {
            int r = row0 + wm * 32 + mt * 16 + grp + h * 8;
#pragma unroll
            for (int nt = 0; nt < 8; nt++) {
                int c = col0 + wn * 64 + nt * 8 + tig * 2;
                if (c     <= r) out[(size_t)r * S_ + c]     = acc[mt][nt][h * 2]     * SCALE_;
                if (c + 1 <= r) out[(size_t)r * S_ + c + 1] = acc[mt][nt][h * 2 + 1] * SCALE_;
            }
        }
}

// ================= out = P @ V (causal k-limit) =================
__global__ __launch_bounds__(256) void pv_mma(
    const float* __restrict__ scores, const float* __restrict__ vh,
    float* __restrict__ out) {
    int bh = blockIdx.z;
    int b = bh >> 4, hd = bh & 15;
    int bm = blockIdx.y;
    const float* Ap = scores + (size_t)bh * S_ * S_;
    const float* Bv = vh + (size_t)bh * S_ * VD_;
    __shared__ unsigned As[2][16][SA];
    __shared__ unsigned Bs[2][16][SB];
    int t = threadIdx.x, lane = t & 31, w = t >> 5;
    int wm = w & 3, wn = w >> 2;
    int row0 = bm * 128;
    int grp = lane >> 2, tig = lane & 3;

    float acc[2][8][4];
#pragma unroll
    for (int mt = 0; mt < 2; mt++)
#pragma unroll
        for (int nt = 0; nt < 8; nt++)
#pragma unroll
            for (int i = 0; i < 4; i++) acc[mt][nt][i] = 0.f;

    float4 ar[2], br[2];
    auto load = [&](int kt) {
        int k0 = kt << 4;
#pragma unroll
        for (int i = 0; i < 2; i++) {
            int idx = i * 256 + t;
            int m = idx >> 2, c4 = (idx & 3) << 2;
            ar[i] = *(const float4*)&Ap[(size_t)(row0 + m) * S_ + k0 + c4];
            int kr = idx >> 5, n4 = (idx & 31) << 2;
            br[i] = *(const float4*)&Bv[(size_t)(k0 + kr) * VD_ + n4];
        }
    };
    auto stor = [&](int buf) {
#pragma unroll
        for (int i = 0; i < 2; i++) {
            int idx = i * 256 + t;
            int m = idx >> 2, c4 = (idx & 3) << 2;
            As[buf][c4 + 0][m] = f2tf(ar[i].x);
            As[buf][c4 + 1][m] = f2tf(ar[i].y);
            As[buf][c4 + 2][m] = f2tf(ar[i].z);
            As[buf][c4 + 3][m] = f2tf(ar[i].w);
            int kr = idx >> 5, n4 = (idx & 31) << 2;
            Bs[buf][kr][n4 + 0] = f2tf(br[i].x);
            Bs[buf][kr][n4 + 1] = f2tf(br[i].y);
            Bs[buf][kr][n4 + 2] = f2tf(br[i].z);
            Bs[buf][kr][n4 + 3] = f2tf(br[i].w);
        }
    };

    int KT = (bm + 1) * 8;   // (row0+128)/16
    load(0); stor(0); __syncthreads();
    int buf = 0;
    for (int kt = 0; kt < KT; kt++) {
        if (kt + 1 < KT) load(kt + 1);
#pragma unroll
        for (int kk = 0; kk < 16; kk += 8) {
            unsigned af[2][4], bf[8][2];
#pragma unroll
            for (int mt = 0; mt < 2; mt++) {
                int mr = wm * 32 + mt * 16 + grp;
                af[mt][0] = As[buf][kk + tig][mr];
                af[mt][1] = As[buf][kk + tig][mr + 8];
                af[mt][2] = As[buf][kk + tig + 4][mr];
                af[mt][3] = As[buf][kk + tig + 4][mr + 8];
            }
#pragma unroll
            for (int nt = 0; nt < 8; nt++) {
                int nc = wn * 64 + nt * 8 + grp;
                bf[nt][0] = Bs[buf][kk + tig][nc];
                bf[nt][1] = Bs[buf][kk + tig + 4][nc];
            }
#pragma unroll
            for (int mt = 0; mt < 2; mt++)
#pragma unroll
                for (int nt = 0; nt < 8; nt++) MMA_TF32(acc[mt][nt], af[mt], bf[nt]);
        }
        if (kt + 1 < KT) stor(buf ^ 1);
        __syncthreads();
        buf ^= 1;
    }
#pragma unroll
    for (int mt = 0; mt < 2; mt++)
#pragma unroll
        for (int h = 0; h < 2; h++) {
            int r = row0 + wm * 32 + mt * 16 + grp + h * 8;
#pragma unroll
            for (int nt = 0; nt < 8; nt++) {
                int c = wn * 64 + nt * 8 + tig * 2;
                *(float2*)&out[(size_t)(b * S_ + r) * H_ + hd * VD_ + c] =
                    make_float2(acc[mt][nt][h * 2], acc[mt][nt][h * 2 + 1]);
            }
        }
}

// ---------------- rmsnorm ----------------
__global__ void rms_kernel(const float* __restrict__ in, const float* __restrict__ w,
                           float* __restrict__ out, int D, int in_stride, int out_stride) {
    int tk = blockIdx.x;
    const float* x = in + (size_t)tk * in_stride;
    float* y = out + (size_t)tk * out_stride;
    int tid = threadIdx.x;
    float ss = 0.f;
    for (int j = tid; j < D; j += blockDim.x) { float v = x[j]; ss += v * v; }
    __shared__ float red[256];
    red[tid] = ss; __syncthreads();
    for (int s = 128; s > 0; s >>= 1) { if (tid < s) red[tid] += red[tid + s]; __syncthreads(); }
    float scale = rsqrtf(red[0] / (float)D + EPS_);
    for (int j = tid; j < D; j += blockDim.x) y[j] = x[j] * scale * w[j];
}

// ---------------- assemble + RoPE ----------------
__global__ void assemble_kernel(const float* __restrict__ q, const float* __restrict__ kv,
                                const float* __restrict__ ckv,
                                const float* __restrict__ cosT, const float* __restrict__ sinT,
                                const int* __restrict__ pos_ids,
                                float* __restrict__ qh, float* __restrict__ kh,
                                float* __restrict__ vh) {
    int tk = blockIdx.x;
    int b = tk / S_, s = tk % S_;
    int tid = threadIdx.x;
    int pos = pos_ids[tk];
    __shared__ float kpe[ROPE_];
    if (tid < 32) {
        int j = tid;
        float x0 = ckv[(size_t)tk * (KVLR_ + ROPE_) + KVLR_ + 2 * j];
        float x1 = ckv[(size_t)tk * (KVLR_ + ROPE_) + KVLR_ + 2 * j + 1];
        float c0 = cosT[pos * ROPE_ + j],      sn0 = sinT[pos * ROPE_ + j];
        float c1 = cosT[pos * ROPE_ + 32 + j], sn1 = sinT[pos * ROPE_ + 32 + j];
        kpe[j]      = x0 * c0 - x1 * sn0;
        kpe[32 + j] = x1 * c1 + x0 * sn1;
    }
    __syncthreads();
    for (int idx = tid; idx < NH_ * QHD_; idx += blockDim.x) {
        int h = idx / QHD_, d = idx % QHD_;
        size_t dst = ((size_t)(b * NH_ + h) * S_ + s) * QHD_ + d;
        float qv;
        if (d < NOPE_) {
            qv = q[(size_t)tk * (NH_ * QHD_) + h * QHD_ + d];
        } else {
            int j = d - NOPE_;
            int jj = (j < 32) ? j : j - 32;
            float x0 = q[(size_t)tk * (NH_ * QHD_) + h * QHD_ + NOPE_ + 2 * jj];
            float x1 = q[(size_t)tk * (NH_ * QHD_) + h * QHD_ + NOPE_ + 2 * jj + 1];
            float c = cosT[pos * ROPE_ + j], sn = sinT[pos * ROPE_ + j];
            qv = (j < 32) ? (x0 * c - x1 * sn) : (x1 * c + x0 * sn);
        }
        qh[dst] = qv;
        float kval = (d < NOPE_) ? kv[(size_t)tk * (NH_ * 256) + h * 256 + d] : kpe[d - NOPE_];
        kh[dst] = kval;
    }
    for (int idx = tid; idx < NH_ * VD_; idx += blockDim.x) {
        int h = idx / VD_, d = idx % VD_;
        vh[((size_t)(b * NH_ + h) * S_ + s) * VD_ + d] =
            kv[(size_t)tk * (NH_ * 256) + h * 256 + NOPE_ + d];
    }
}

// ---------------- softmax ----------------
__global__ void softmax_kernel(float* __restrict__ scores, const int* __restrict__ amask) {
    int row = blockIdx.x;
    int i = row % S_;
    int bh = row / S_;
    int b = bh / NH_;
    float* p = scores + (size_t)row * S_;
    int len = i + 1;
    int tid = threadIdx.x;
    __shared__ float red[256];
    float m = -3.0e38f;
    for (int j = tid; j < len; j += 256) {
        float v = (amask[b * S_ + j] != 0) ? p[j] : -3.0e38f;
        m = fmaxf(m, v);
    }
    red[tid] = m; __syncthreads();
    for (int s = 128; s > 0; s >>= 1) { if (tid < s) red[tid] = fmaxf(red[tid], red[tid + s]); __syncthreads(); }
    m = red[0]; __syncthreads();
    float sum = 0.f;
    for (int j = tid; j < len; j += 256) {
        float v = (amask[b * S_ + j] != 0) ? p[j] : -3.0e38f;
        float e = expf(v - m);
        p[j] = e;
        sum += e;
    }
    red[tid] = sum; __syncthreads();
    for (int s = 128; s > 0; s >>= 1) { if (tid < s) red[tid] += red[tid + s]; __syncthreads(); }
    float inv = 1.f / red[0];
    for (int j = tid; j < len; j += 256) p[j] *= inv;
    for (int j = len + tid; j < S_; j += 256) p[j] = 0.f;
}

// ---------------- launch ----------------
extern "C" void kernel_launch(void* const* d_in, const int* in_sizes, int n_in,
                              void* d_out, int out_size) {
    const float* hidden   = (const float*)d_in[0];
    const float* sinT     = (const float*)d_in[1];
    const float* cosT     = (const float*)d_in[2];
    const int*   pos_ids  = (const int*)  d_in[3];
    const int*   amask    = (const int*)  d_in[4];
    const float* in_ln_w  = (const float*)d_in[5];
    const float* q_a_w    = (const float*)d_in[6];
    const float* q_a_ln_w = (const float*)d_in[7];
    const float* q_b_w    = (const float*)d_in[8];
    const float* kv_a_w   = (const float*)d_in[9];
    const float* kv_a_ln_w= (const float*)d_in[10];
    const float* kv_b_w   = (const float*)d_in[11];
    const float* o_w      = (const float*)d_in[12];
    const float* post_ln_w= (const float*)d_in[13];
    const float* gate_w   = (const float*)d_in[14];
    const float* up_w     = (const float*)d_in[15];
    const float* down_w   = (const float*)d_in[16];
    float* outp = (float*)d_out;

    float *x, *qa, *q, *ckv, *ckvn, *kv, *qh, *kh, *vh, *scores, *attnout, *h1, *y, *gate, *act;
    cudaGetSymbolAddress((void**)&x, g_x);
    cudaGetSymbolAddress((void**)&qa, g_qa);
    cudaGetSymbolAddress((void**)&q, g_q);
    cudaGetSymbolAddress((void**)&ckv, g_ckv);
    cudaGetSymbolAddress((void**)&ckvn, g_ckvn);
    cudaGetSymbolAddress((void**)&kv, g_kv);
    cudaGetSymbolAddress((void**)&qh, g_qh);
    cudaGetSymbolAddress((void**)&kh, g_kh);
    cudaGetSymbolAddress((void**)&vh, g_vh);
    cudaGetSymbolAddress((void**)&scores, g_scores);
    cudaGetSymbolAddress((void**)&attnout, g_attnout);
    cudaGetSymbolAddress((void**)&h1, g_h1);
    cudaGetSymbolAddress((void**)&y, g_y);
    cudaGetSymbolAddress((void**)&gate, g_gate);
    cudaGetSymbolAddress((void**)&act, g_act);

    rms_kernel<<<T_, 256>>>(hidden, in_ln_w, x, H_, H_, H_);
    gemm_mma<0><<<dim3(QLR_/128, T_/128), 256>>>(x, q_a_w, qa, nullptr, T_, QLR_, H_);
    rms_kernel<<<T_, 256>>>(qa, q_a_ln_w, qa, QLR_, QLR_, QLR_);
    gemm_mma<0><<<dim3(NH_*QHD_/128, T_/128), 256>>>(qa, q_b_w, q, nullptr, T_, NH_*QHD_, QLR_);
    gemm_mma<0><<<dim3((KVLR_+ROPE_+127)/128, T_/128), 256>>>(x, kv_a_w, ckv, nullptr, T_, KVLR_+ROPE_, H_);
    rms_kernel<<<T_, 256>>>(ckv, kv_a_ln_w, ckvn, KVLR_, KVLR_+ROPE_, KVLR_);
    gemm_mma<0><<<dim3(NH_*256/128, T_/128), 256>>>(ckvn, kv_b_w, kv, nullptr, T_, NH_*256, KVLR_);
    assemble_kernel<<<T_, 256>>>(q, kv, ckv, cosT, sinT, pos_ids, qh, kh, vh);
    score_mma<<<dim3(S_/128, S_/128, B_*NH_), 256>>>(qh, kh, scores);
    softmax_kernel<<<B_*NH_*S_, 256>>>(scores, amask);
    pv_mma<<<dim3(1, S_/128, B_*NH_), 256>>>(scores, vh, attnout);
    gemm_mma<1><<<dim3(H_/128, T_/128), 256>>>(attnout, o_w, h1, hidden, T_, H_, H_);
    rms_kernel<<<T_, 256>>>(h1, post_ln_w, y, H_, H_, H_);
    gemm_mma<0><<<dim3(I_/128, T_/128), 256>>>(y, gate_w, gate, nullptr, T_, I_, H_);
    gemm_mma<2><<<dim3(I_/128, T_/128), 256>>>(y, up_w, act, gate, T_, I_, H_);
    gemm_mma<1><<<dim3(H_/128, T_/128), 256>>>(act, down_w, outp, h1, T_, H_, I_);
    (void)in_sizes; (void)n_in; (void)out_size;
}